// round 7
// baseline (speedup 1.0000x reference)
#include <cuda_runtime.h>
#include <math.h>
#include <stdint.h>

// Problem constants
#define BB     2
#define SEQ    2048
#define DIM    2048
#define HH     16
#define QLORA  512
#define KVLORA 512
#define DNOPE  128
#define DROPE  64
#define DV     128
#define DQK    192          // DNOPE + DROPE
#define DKV    256          // DNOPE + DV
#define BSROWS (BB*SEQ)     // 4096
#define SCALEF 0.07216878364870323f   // 192^-0.5

// ---------------- scratch (device globals; allocation-free) ----------------
__device__ float g_qa  [(size_t)BSROWS*QLORA];
__device__ float g_qn  [(size_t)BSROWS*QLORA];
__device__ float g_q   [(size_t)BSROWS*HH*DQK];
__device__ float g_kva [(size_t)BSROWS*(KVLORA+DROPE)];
__device__ float g_kvn [(size_t)BSROWS*KVLORA];
__device__ float g_kvb [(size_t)BSROWS*HH*DKV];
__device__ float g_k   [(size_t)BSROWS*HH*DQK];
__device__ float g_ao  [(size_t)BSROWS*HH*DV];
__device__ float g_part[(size_t)4*BSROWS*(KVLORA+DROPE)];   // split-K partials

// --------------------------- tf32 helpers ----------------------------------
__device__ __forceinline__ uint32_t f2tf32(float x) {
    uint32_t r;
    asm("cvt.rna.tf32.f32 %0, %1;" : "=r"(r) : "f"(x));
    return r;
}
__device__ __forceinline__ float f2tf32f(float x) {
    return __uint_as_float(f2tf32(x));
}
__device__ __forceinline__ void mma_tf32(float* c, const uint32_t* a,
                                         uint32_t b0, uint32_t b1) {
    asm volatile(
        "mma.sync.aligned.m16n8k8.row.col.f32.tf32.tf32.f32 "
        "{%0,%1,%2,%3}, {%4,%5,%6,%7}, {%8,%9}, {%0,%1,%2,%3};"
        : "+f"(c[0]), "+f"(c[1]), "+f"(c[2]), "+f"(c[3])
        : "r"(a[0]), "r"(a[1]), "r"(a[2]), "r"(a[3]), "r"(b0), "r"(b1));
}

// ---------------------------------------------------------------------------
// Batched TF32 tensor-core GEMM: C = alpha * A @ B (+bias)
// Tile 128x128x16, 8 warps 4(M)x2(N), warp tile 32x64, double-buffered smem.
// splitK>1: blockIdx.z = split slice; writes partial C (no bias); K chunked.
// ---------------------------------------------------------------------------
template<bool TRANSB>
__global__ __launch_bounds__(256)
void gemm_tf32(const float* __restrict__ A, const float* __restrict__ Bm,
               const float* __restrict__ bias, float* __restrict__ C,
               int M, int N, int K, int lda, int ldb, int ldc, float alpha,
               int Hdiv, int splitK,
               long sAb, long sAh, long sBb, long sBh, long sCb, long sCh)
{
    const int BM = 128, BN = 128, BK = 16;
    __shared__ float As[2][BK][BM + 4];
    __shared__ float Bs[2][BK][BN + 4];

    const int bz = blockIdx.z;
    if (splitK > 1) {
        int chunk = K / splitK;
        A  += (size_t)bz * chunk;
        if (TRANSB) Bm += (size_t)bz * chunk;
        else        Bm += (size_t)bz * chunk * ldb;
        C  += (size_t)bz * sCb;
        K = chunk;
    } else {
        int b = bz / Hdiv, h = bz % Hdiv;
        A  += (size_t)b * sAb + (size_t)h * sAh;
        Bm += (size_t)b * sBb + (size_t)h * sBh;
        C  += (size_t)b * sCb + (size_t)h * sCh;
    }

    const int tid  = threadIdx.x;
    const int warp = tid >> 5;
    const int lane = tid & 31;
    const int wm   = warp >> 1;
    const int wn   = warp & 1;
    const int gid  = lane >> 2;
    const int tg   = lane & 3;

    const int row0 = blockIdx.y * BM;
    const int col0 = blockIdx.x * BN;

    const int nIter = (K + BK - 1) / BK;

    float acc[2][8][4];
#pragma unroll
    for (int mt = 0; mt < 2; mt++)
#pragma unroll
        for (int nt = 0; nt < 8; nt++)
#pragma unroll
            for (int r = 0; r < 4; r++) acc[mt][nt][r] = 0.f;

    float4 rA[2], rB[2];

    auto gloadA = [&](int k0) {
#pragma unroll
        for (int i = 0; i < 2; i++) {
            int id = tid * 2 + i;
            int m  = id >> 2, kq = id & 3;
            int gr = row0 + m, gk = k0 + kq * 4;
            rA[i] = make_float4(0.f, 0.f, 0.f, 0.f);
            if (gr < M && gk < K)
                rA[i] = *(const float4*)(A + (size_t)gr * lda + gk);
        }
    };
    auto gloadB = [&](int k0) {
#pragma unroll
        for (int i = 0; i < 2; i++) {
            rB[i] = make_float4(0.f, 0.f, 0.f, 0.f);
            if (TRANSB) {
                int id = tid * 2 + i;
                int n  = id >> 2, kq = id & 3;
                int gn = col0 + n, gk = k0 + kq * 4;
                if (gn < N && gk < K)
                    rB[i] = *(const float4*)(Bm + (size_t)gn * ldb + gk);
            } else {
                int id = tid * 2 + i;
                int kk = id >> 5, nq = id & 31;
                int gk = k0 + kk, gn = col0 + nq * 4;
                if (gk < K && gn < N)
                    rB[i] = *(const float4*)(Bm + (size_t)gk * ldb + gn);
            }
        }
    };
    auto stsA = [&](int s) {
#pragma unroll
        for (int i = 0; i < 2; i++) {
            int id = tid * 2 + i;
            int m  = id >> 2, kq = id & 3;
            As[s][kq * 4 + 0][m] = f2tf32f(rA[i].x);
            As[s][kq * 4 + 1][m] = f2tf32f(rA[i].y);
            As[s][kq * 4 + 2][m] = f2tf32f(rA[i].z);
            As[s][kq * 4 + 3][m] = f2tf32f(rA[i].w);
        }
    };
    auto stsB = [&](int s) {
#pragma unroll
        for (int i = 0; i < 2; i++) {
            if (TRANSB) {
                int id = tid * 2 + i;
                int n  = id >> 2, kq = id & 3;
                Bs[s][kq * 4 + 0][n] = f2tf32f(rB[i].x);
                Bs[s][kq * 4 + 1][n] = f2tf32f(rB[i].y);
                Bs[s][kq * 4 + 2][n] = f2tf32f(rB[i].z);
                Bs[s][kq * 4 + 3][n] = f2tf32f(rB[i].w);
            } else {
                int id = tid * 2 + i;
                int kk = id >> 5, nq = id & 31;
                float4 v = make_float4(f2tf32f(rB[i].x), f2tf32f(rB[i].y),
                                       f2tf32f(rB[i].z), f2tf32f(rB[i].w));
                *(float4*)&Bs[s][kk][nq * 4] = v;
            }
        }
    };

    gloadA(0); gloadB(0);
    stsA(0);   stsB(0);
    __syncthreads();

    for (int it = 0; it < nIter; it++) {
        const int s = it & 1;
        if (it + 1 < nIter) { gloadA((it + 1) * BK); gloadB((it + 1) * BK); }

#pragma unroll
        for (int ks = 0; ks < 2; ks++) {
            const int kb = ks * 8;
            uint32_t af[2][4];
#pragma unroll
            for (int mt = 0; mt < 2; mt++) {
                int mr = wm * 32 + mt * 16 + gid;
                af[mt][0] = __float_as_uint(As[s][kb + tg    ][mr    ]);
                af[mt][1] = __float_as_uint(As[s][kb + tg    ][mr + 8]);
                af[mt][2] = __float_as_uint(As[s][kb + tg + 4][mr    ]);
                af[mt][3] = __float_as_uint(As[s][kb + tg + 4][mr + 8]);
            }
#pragma unroll
            for (int nt = 0; nt < 8; nt++) {
                int nc = wn * 64 + nt * 8 + gid;
                uint32_t b0 = __float_as_uint(Bs[s][kb + tg    ][nc]);
                uint32_t b1 = __float_as_uint(Bs[s][kb + tg + 4][nc]);
                mma_tf32(acc[0][nt], af[0], b0, b1);
                mma_tf32(acc[1][nt], af[1], b0, b1);
            }
        }

        if (it + 1 < nIter) { stsA(s ^ 1); stsB(s ^ 1); }
        __syncthreads();
    }

#pragma unroll
    for (int mt = 0; mt < 2; mt++) {
        int gr = row0 + wm * 32 + mt * 16 + gid;
#pragma unroll
        for (int nt = 0; nt < 8; nt++) {
            int gc = col0 + wn * 64 + nt * 8 + 2 * tg;
            if (gc >= N) continue;
            float bx = 0.f, by = 0.f;
            if (bias) { bx = bias[gc]; by = bias[gc + 1]; }
#pragma unroll
            for (int rr = 0; rr < 2; rr++) {
                int r = gr + rr * 8;
                if (r >= M) continue;
                float v0 = acc[mt][nt][rr * 2 + 0] * alpha + bx;
                float v1 = acc[mt][nt][rr * 2 + 1] * alpha + by;
                *(float2*)&C[(size_t)r * ldc + gc] = make_float2(v0, v1);
            }
        }
    }
}

// ---------------------- split-K reduce (fixed order, deterministic) --------
__global__ void reduce_splitk(const float* __restrict__ part,
                              const float* __restrict__ bias,
                              float* __restrict__ out,
                              int total, int N, int nsplit)
{
    int i = (blockIdx.x * blockDim.x + threadIdx.x) * 4;
    if (i >= total) return;
    float4 s = *(const float4*)(part + i);
    for (int k = 1; k < nsplit; k++) {
        float4 p = *(const float4*)(part + (size_t)k * total + i);
        s.x += p.x; s.y += p.y; s.z += p.z; s.w += p.w;
    }
    if (bias) {
        int c = i % N;
        s.x += bias[c]; s.y += bias[c + 1]; s.z += bias[c + 2]; s.w += bias[c + 3];
    }
    *(float4*)(out + i) = s;
}

// ---------------------------------------------------------------------------
// Fused flash attention (causal): per CTA one (b,h,128-query tile).
// 8 warps x 16 query rows. 64-key tiles. tf32 mma for S=QK^T and O=P V.
// Online softmax per-warp (rows live within one warp; shfl over tg lanes).
// ---------------------------------------------------------------------------
#define FA_SQ_LD 136
#define FA_SK_LD 72
#define FA_SV_LD 136
#define FA_SP_LD 136
#define FA_SMEM_FLOATS (192*FA_SQ_LD + 192*FA_SK_LD + 64*FA_SV_LD + 64*FA_SP_LD)

__global__ __launch_bounds__(256)
void fa_kernel(const float* __restrict__ Qg, const float* __restrict__ Kg,
               const float* __restrict__ Vg, float* __restrict__ Og)
{
    extern __shared__ float sm[];
    float* sQ = sm;                         // [192][136]  (k-major)
    float* sK = sQ + 192 * FA_SQ_LD;        // [192][72]   (k-major)
    float* sV = sK + 192 * FA_SK_LD;        // [64][136]   (key-major)
    float* sP = sV + 64 * FA_SV_LD;         // [64][136]   (key-major)

    const int qt = (int)(gridDim.x - 1 - blockIdx.x);   // big tiles first
    const int bh = blockIdx.y;
    const int b  = bh / HH;
    const int h  = bh % HH;

    const int tid  = threadIdx.x;
    const int warp = tid >> 5;
    const int lane = tid & 31;
    const int gid  = lane >> 2;
    const int tg   = lane & 3;
    const int qr0  = warp * 16;             // warp's local query row base
    const int qg0  = qt * 128;              // CTA's global query base

    const float* Qbase = Qg + ((size_t)(b * SEQ + qg0) * HH + h) * DQK;
    const float* Kbase = Kg + ((size_t)(b * SEQ) * HH + h) * DQK;
    const float* Vbase = Vg + ((size_t)(b * SEQ) * HH + h) * DKV + DNOPE;

    // load Q tile [128][192] -> sQ[k][m], tf32
#pragma unroll
    for (int i = 0; i < 24; i++) {
        int idx = tid + i * 256;            // 6144 float4s
        int row = idx / 48, c4 = idx % 48;
        float4 v = *(const float4*)(Qbase + (size_t)row * (HH * DQK) + c4 * 4);
        sQ[(c4 * 4 + 0) * FA_SQ_LD + row] = f2tf32f(v.x);
        sQ[(c4 * 4 + 1) * FA_SQ_LD + row] = f2tf32f(v.y);
        sQ[(c4 * 4 + 2) * FA_SQ_LD + row] = f2tf32f(v.z);
        sQ[(c4 * 4 + 3) * FA_SQ_LD + row] = f2tf32f(v.w);
    }

    float accO[16][4];
#pragma unroll
    for (int nt = 0; nt < 16; nt++)
#pragma unroll
        for (int r = 0; r < 4; r++) accO[nt][r] = 0.f;
    float m_i[2] = { -1e30f, -1e30f };
    float l_i[2] = { 0.f, 0.f };

    const int ktEnd = 2 * qt + 2;
    const int warpRowMax = qg0 + qr0 + 15;

    for (int kt = 0; kt < ktEnd; kt++) {
        const int kb0 = kt * 64;
        __syncthreads();    // previous compute done before smem overwrite

        // load K tile [64 keys][192] -> sK[k][key]
#pragma unroll
        for (int i = 0; i < 12; i++) {
            int idx = tid + i * 256;        // 3072 float4s
            int key = idx / 48, c4 = idx % 48;
            float4 v = *(const float4*)(Kbase + (size_t)(kb0 + key) * (HH * DQK) + c4 * 4);
            sK[(c4 * 4 + 0) * FA_SK_LD + key] = f2tf32f(v.x);
            sK[(c4 * 4 + 1) * FA_SK_LD + key] = f2tf32f(v.y);
            sK[(c4 * 4 + 2) * FA_SK_LD + key] = f2tf32f(v.z);
            sK[(c4 * 4 + 3) * FA_SK_LD + key] = f2tf32f(v.w);
        }
        // load V tile [64 keys][128] -> sV[key][dv]
#pragma unroll
        for (int i = 0; i < 8; i++) {
            int idx = tid + i * 256;        // 2048 float4s
            int key = idx / 32, c4 = idx % 32;
            float4 v = *(const float4*)(Vbase + (size_t)(kb0 + key) * (HH * DKV) + c4 * 4);
            float4 t = make_float4(f2tf32f(v.x), f2tf32f(v.y), f2tf32f(v.z), f2tf32f(v.w));
            *(float4*)&sV[key * FA_SV_LD + c4 * 4] = t;
        }
        __syncthreads();

        if (kb0 > warpRowMax) continue;     // warp-uniform: fully masked tile

        // ---- S = Q K^T on this tile ----
        float accS[8][4];
#pragma unroll
        for (int nt = 0; nt < 8; nt++)
#pragma unroll
            for (int r = 0; r < 4; r++) accS[nt][r] = 0.f;

#pragma unroll
        for (int ks = 0; ks < 24; ks++) {
            const int kb = ks * 8;
            uint32_t a[4];
            a[0] = __float_as_uint(sQ[(kb + tg    ) * FA_SQ_LD + qr0 + gid    ]);
            a[1] = __float_as_uint(sQ[(kb + tg    ) * FA_SQ_LD + qr0 + gid + 8]);
            a[2] = __float_as_uint(sQ[(kb + tg + 4) * FA_SQ_LD + qr0 + gid    ]);
            a[3] = __float_as_uint(sQ[(kb + tg + 4) * FA_SQ_LD + qr0 + gid + 8]);
#pragma unroll
            for (int nt = 0; nt < 8; nt++) {
                uint32_t b0 = __float_as_uint(sK[(kb + tg    ) * FA_SK_LD + nt * 8 + gid]);
                uint32_t b1 = __float_as_uint(sK[(kb + tg + 4) * FA_SK_LD + nt * 8 + gid]);
                mma_tf32(accS[nt], a, b0, b1);
            }
        }

        // ---- online softmax (per half: rows gid, gid+8) ----
#pragma unroll
        for (int h2 = 0; h2 < 2; h2++) {
            const int rg = qg0 + qr0 + gid + 8 * h2;
            float rmax = -1e30f;
#pragma unroll
            for (int nt = 0; nt < 8; nt++) {
#pragma unroll
                for (int j = 0; j < 2; j++) {
                    int col = kb0 + nt * 8 + tg * 2 + j;
                    float s = accS[nt][h2 * 2 + j] * SCALEF;
                    if (col > rg) s = -1e30f;
                    accS[nt][h2 * 2 + j] = s;
                    rmax = fmaxf(rmax, s);
                }
            }
            rmax = fmaxf(rmax, __shfl_xor_sync(0xffffffffu, rmax, 1));
            rmax = fmaxf(rmax, __shfl_xor_sync(0xffffffffu, rmax, 2));
            float mold = m_i[h2];
            float mnew = fmaxf(mold, rmax);
            float f = expf(mold - mnew);
            float rsum = 0.f;
#pragma unroll
            for (int nt = 0; nt < 8; nt++) {
#pragma unroll
                for (int j = 0; j < 2; j++) {
                    float p = expf(accS[nt][h2 * 2 + j] - mnew);
                    accS[nt][h2 * 2 + j] = p;
                    rsum += p;
                }
            }
            rsum += __shfl_xor_sync(0xffffffffu, rsum, 1);
            rsum += __shfl_xor_sync(0xffffffffu, rsum, 2);
            l_i[h2] = l_i[h2] * f + rsum;
            m_i[h2] = mnew;
#pragma unroll
            for (int nt = 0; nt < 16; nt++) {
                accO[nt][h2 * 2 + 0] *= f;
                accO[nt][h2 * 2 + 1] *= f;
            }
            // write P (tf32) -> sP[key_local][qrow_local]
#pragma unroll
            for (int nt = 0; nt < 8; nt++) {
                int cl = nt * 8 + tg * 2;
                sP[(cl    ) * FA_SP_LD + qr0 + gid + 8 * h2] = f2tf32f(accS[nt][h2 * 2 + 0]);
                sP[(cl + 1) * FA_SP_LD + qr0 + gid + 8 * h2] = f2tf32f(accS[nt][h2 * 2 + 1]);
            }
        }
        __syncwarp();

        // ---- O += P V ----
#pragma unroll
        for (int ks = 0; ks < 8; ks++) {
            const int kb = ks * 8;
            uint32_t a[4];
            a[0] = __float_as_uint(sP[(kb + tg    ) * FA_SP_LD + qr0 + gid    ]);
            a[1] = __float_as_uint(sP[(kb + tg    ) * FA_SP_LD + qr0 + gid + 8]);
            a[2] = __float_as_uint(sP[(kb + tg + 4) * FA_SP_LD + qr0 + gid    ]);
            a[3] = __float_as_uint(sP[(kb + tg + 4) * FA_SP_LD + qr0 + gid + 8]);
#pragma unroll
            for (int nt = 0; nt < 16; nt++) {
                uint32_t b0 = __float_as_uint(sV[(kb + tg    ) * FA_SV_LD + nt * 8 + gid]);
                uint32_t b1 = __float_as_uint(sV[(kb + tg + 4) * FA_SV_LD + nt * 8 + gid]);
                mma_tf32(accO[nt], a, b0, b1);
            }
        }
    }

    // ---- epilogue: O / l ----
#pragma unroll
    for (int h2 = 0; h2 < 2; h2++) {
        const int rg = qg0 + qr0 + gid + 8 * h2;
        float inv = 1.f / l_i[h2];
        float* Orow = Og + ((size_t)(b * SEQ + rg) * HH + h) * DV;
#pragma unroll
        for (int nt = 0; nt < 16; nt++) {
            float2 v = make_float2(accO[nt][h2 * 2 + 0] * inv,
                                   accO[nt][h2 * 2 + 1] * inv);
            *(float2*)&Orow[nt * 8 + tg * 2] = v;
        }
    }
}

// ------------------------------ RMSNorm ------------------------------------
__global__ void rmsnorm_kernel(const float* __restrict__ in,
                               const float* __restrict__ w,
                               float* __restrict__ out,
                               int n, int in_stride, int out_stride)
{
    int row = blockIdx.x;
    const float* x = in + (size_t)row * in_stride;
    float* y = out + (size_t)row * out_stride;
    int tid = threadIdx.x;

    float ss = 0.f;
    for (int i = tid; i < n; i += blockDim.x) { float v = x[i]; ss += v * v; }
#pragma unroll
    for (int o = 16; o > 0; o >>= 1) ss += __shfl_xor_sync(0xffffffffu, ss, o);
    __shared__ float red[8];
    if ((tid & 31) == 0) red[tid >> 5] = ss;
    __syncthreads();
    if (tid == 0) {
        float v = 0.f;
        for (int wgi = 0; wgi < (int)(blockDim.x >> 5); wgi++) v += red[wgi];
        red[0] = v;
    }
    __syncthreads();
    float inv = rsqrtf(red[0] / (float)n + 1e-6f);
    for (int i = tid; i < n; i += blockDim.x) y[i] = x[i] * inv * w[i];
}

// -------------------------- RoPE on q_pe (in place) -------------------------
__global__ void rope_q_kernel(float* __restrict__ q,
                              const float* __restrict__ fcos,
                              const float* __restrict__ fsin)
{
    int idx = blockIdx.x * blockDim.x + threadIdx.x;
    const int HALF = DROPE / 2;
    int total = BSROWS * HH * HALF;
    if (idx >= total) return;
    int i  = idx % HALF;
    int hh = (idx / HALF) % HH;
    int bs = idx / (HALF * HH);
    int s  = bs % SEQ;
    float c  = fcos[s * HALF + i];
    float sn = fsin[s * HALF + i];
    float* p = q + (size_t)bs * (HH * DQK) + hh * DQK + DNOPE + 2 * i;
    float x0 = p[0], x1 = p[1];
    p[0] = x0 * c - x1 * sn;
    p[1] = x0 * sn + x1 * c;
}

// ---------------- build K = concat(k_nope, rope(k_pe) broadcast) ------------
__global__ void build_k_kernel(const float* __restrict__ kvb,
                               const float* __restrict__ kva,
                               const float* __restrict__ fcos,
                               const float* __restrict__ fsin,
                               float* __restrict__ kk)
{
    const int HALF  = DROPE / 2;
    const int UNITS = DNOPE + HALF;
    int idx = blockIdx.x * blockDim.x + threadIdx.x;
    int total = BSROWS * HH * UNITS;
    if (idx >= total) return;
    int u  = idx % UNITS;
    int hh = (idx / UNITS) % HH;
    int bs = idx / (UNITS * HH);
    int s  = bs % SEQ;
    float* krow = kk + (size_t)bs * (HH * DQK) + hh * DQK;
    if (u < DNOPE) {
        krow[u] = kvb[(size_t)bs * (HH * DKV) + hh * DKV + u];
    } else {
        int i = u - DNOPE;
        float c  = fcos[s * HALF + i];
        float sn = fsin[s * HALF + i];
        const float* kp = kva + (size_t)bs * (KVLORA + DROPE) + KVLORA;
        float x0 = kp[2 * i], x1 = kp[2 * i + 1];
        krow[DNOPE + 2 * i]     = x0 * c - x1 * sn;
        krow[DNOPE + 2 * i + 1] = x0 * sn + x1 * c;
    }
}

// -----------------------------------------------------------------------------
extern "C" void kernel_launch(void* const* d_in, const int* in_sizes, int n_in,
                              void* d_out, int out_size)
{
    (void)in_sizes; (void)n_in; (void)out_size;
    const float* x        = (const float*)d_in[0];
    const float* wq_a_w   = (const float*)d_in[1];
    const float* wq_a_b   = (const float*)d_in[2];
    const float* q_norm_w = (const float*)d_in[3];
    const float* wq_b_w   = (const float*)d_in[4];
    const float* wkv_a_w  = (const float*)d_in[5];
    const float* wkv_a_b  = (const float*)d_in[6];
    const float* kv_norm_w= (const float*)d_in[7];
    const float* wkv_b_w  = (const float*)d_in[8];
    const float* wo_w     = (const float*)d_in[9];
    const float* fcos     = (const float*)d_in[10];
    const float* fsin     = (const float*)d_in[11];
    float* out = (float*)d_out;

    float *qa, *qn, *qbuf, *kva, *kvn, *kvb, *kmat, *ao, *part;
    cudaGetSymbolAddress((void**)&qa,   g_qa);
    cudaGetSymbolAddress((void**)&qn,   g_qn);
    cudaGetSymbolAddress((void**)&qbuf, g_q);
    cudaGetSymbolAddress((void**)&kva,  g_kva);
    cudaGetSymbolAddress((void**)&kvn,  g_kvn);
    cudaGetSymbolAddress((void**)&kvb,  g_kvb);
    cudaGetSymbolAddress((void**)&kmat, g_k);
    cudaGetSymbolAddress((void**)&ao,   g_ao);
    cudaGetSymbolAddress((void**)&part, g_part);

    cudaFuncSetAttribute(fa_kernel, cudaFuncAttributeMaxDynamicSharedMemorySize,
                         FA_SMEM_FLOATS * 4);

    dim3 blk(256);

    // 1. q_a = x @ wq_a_w (split-K x4)           [4096,512] K=2048
    gemm_tf32<false><<<dim3(4,32,4), blk>>>(
        x, wq_a_w, nullptr, part,
        BSROWS, QLORA, DIM, DIM, QLORA, QLORA, 1.f, 1, 4,
        0,0,0,0, (long)BSROWS*QLORA, 0);
    reduce_splitk<<<(BSROWS*QLORA/4 + 255)/256, 256>>>(
        part, wq_a_b, qa, BSROWS*QLORA, QLORA, 4);

    // 2. q_norm = rmsnorm(q_a)
    rmsnorm_kernel<<<BSROWS, 256>>>(qa, q_norm_w, qn, QLORA, QLORA, QLORA);

    // 3. q = q_norm @ wq_b_w                     [4096,3072] K=512
    gemm_tf32<false><<<dim3(24,32,1), blk>>>(
        qn, wq_b_w, nullptr, qbuf,
        BSROWS, HH*DQK, QLORA, QLORA, HH*DQK, HH*DQK, 1.f, 1, 1,
        0,0,0,0,0,0);

    // 4. kv_full = x @ wkv_a_w (split-K x4)      [4096,576] K=2048
    gemm_tf32<false><<<dim3(5,32,4), blk>>>(
        x, wkv_a_w, nullptr, part,
        BSROWS, KVLORA+DROPE, DIM, DIM, KVLORA+DROPE, KVLORA+DROPE, 1.f, 1, 4,
        0,0,0,0, (long)BSROWS*(KVLORA+DROPE), 0);
    reduce_splitk<<<(BSROWS*(KVLORA+DROPE)/4 + 255)/256, 256>>>(
        part, wkv_a_b, kva, BSROWS*(KVLORA+DROPE), KVLORA+DROPE, 4);

    // 5. kv_norm = rmsnorm(kv_full[:,:512])
    rmsnorm_kernel<<<BSROWS, 256>>>(kva, kv_norm_w, kvn, KVLORA, KVLORA+DROPE, KVLORA);

    // 6. kv_b = kv_norm @ wkv_b_w                [4096,4096] K=512
    gemm_tf32<false><<<dim3(32,32,1), blk>>>(
        kvn, wkv_b_w, nullptr, kvb,
        BSROWS, HH*DKV, KVLORA, KVLORA, HH*DKV, HH*DKV, 1.f, 1, 1,
        0,0,0,0,0,0);

    // 7. RoPE on q_pe (in place)
    {
        int tot = BSROWS * HH * (DROPE/2);
        rope_q_kernel<<<(tot + 255)/256, 256>>>(qbuf, fcos, fsin);
    }

    // 8. build K = [k_nope | rope(k_pe)]
    {
        int tot = BSROWS * HH * (DNOPE + DROPE/2);
        build_k_kernel<<<(tot + 255)/256, 256>>>(kvb, kva, fcos, fsin, kmat);
    }

    // 9. fused flash attention -> ao
    fa_kernel<<<dim3(SEQ/128, BB*HH), blk, FA_SMEM_FLOATS * 4>>>(
        qbuf, kmat, kvb, ao);

    // 10. out = attn_out @ wo_w                  [4096,2048] K=2048
    gemm_tf32<false><<<dim3(16,32,1), blk>>>(
        ao, wo_w, nullptr, out,
        BSROWS, DIM, HH*DV, HH*DV, DIM, DIM, 1.f, 1, 1,
        0,0,0,0,0,0);
}

// round 11
// speedup vs baseline: 1.1353x; 1.1353x over previous
#include <cuda_runtime.h>
#include <math.h>
#include <stdint.h>

// Problem constants
#define BB     2
#define SEQ    2048
#define DIM    2048
#define HH     16
#define QLORA  512
#define KVLORA 512
#define DNOPE  128
#define DROPE  64
#define DV     128
#define DQK    192          // DNOPE + DROPE
#define DKV    256          // DNOPE + DV
#define BSROWS (BB*SEQ)     // 4096
#define SCALEF 0.07216878364870323f   // 192^-0.5

// ---------------- scratch (device globals; allocation-free) ----------------
__device__ float g_qn  [(size_t)BSROWS*QLORA];
__device__ float g_q   [(size_t)BSROWS*HH*DQK];
__device__ float g_kva [(size_t)BSROWS*(KVLORA+DROPE)];
__device__ float g_kvn [(size_t)BSROWS*KVLORA];
__device__ float g_kvb [(size_t)BSROWS*HH*DKV];
__device__ float g_k   [(size_t)BSROWS*HH*DQK];
__device__ float g_ao  [(size_t)BSROWS*HH*DV];
__device__ float g_part[(size_t)4*BSROWS*(KVLORA+DROPE)];   // split-K partials

// --------------------------- tf32 helpers ----------------------------------
__device__ __forceinline__ uint32_t f2tf32(float x) {
    uint32_t r;
    asm("cvt.rna.tf32.f32 %0, %1;" : "=r"(r) : "f"(x));
    return r;
}
__device__ __forceinline__ float f2tf32f(float x) {
    return __uint_as_float(f2tf32(x));
}
__device__ __forceinline__ void mma_tf32(float* c, const uint32_t* a,
                                         uint32_t b0, uint32_t b1) {
    asm volatile(
        "mma.sync.aligned.m16n8k8.row.col.f32.tf32.tf32.f32 "
        "{%0,%1,%2,%3}, {%4,%5,%6,%7}, {%8,%9}, {%0,%1,%2,%3};"
        : "+f"(c[0]), "+f"(c[1]), "+f"(c[2]), "+f"(c[3])
        : "r"(a[0]), "r"(a[1]), "r"(a[2]), "r"(a[3]), "r"(b0), "r"(b1));
}

// ---------------------------------------------------------------------------
// Batched TF32 tensor-core GEMM v2: C = alpha * A @ B (+bias)
// CTA tile 128x128x16, 128 threads = 4 warps in 2(M) x 2(N); warp tile 64x64.
// K-major smem, stride 136 (%32==8 -> conflict-free fragment LDS).
// Double-buffered smem, float4 LDG register staging, tf32 cvt at STS.
// splitK>1: blockIdx.z = split slice; writes partial C (no bias); K chunked.
// ---------------------------------------------------------------------------
#define GLD 136

template<bool TRANSB>
__global__ __launch_bounds__(128)
void gemm_tf32(const float* __restrict__ A, const float* __restrict__ Bm,
               const float* __restrict__ bias, float* __restrict__ C,
               int M, int N, int K, int lda, int ldb, int ldc, float alpha,
               int Hdiv, int splitK,
               long sAb, long sAh, long sBb, long sBh, long sCb, long sCh)
{
    const int BM = 128, BK = 16;
    __shared__ float As[2][BK * GLD];
    __shared__ float Bs[2][BK * GLD];

    const int bz = blockIdx.z;
    if (splitK > 1) {
        int chunk = K / splitK;
        A  += (size_t)bz * chunk;
        if (TRANSB) Bm += (size_t)bz * chunk;
        else        Bm += (size_t)bz * chunk * ldb;
        C  += (size_t)bz * sCb;
        K = chunk;
    } else {
        int b = bz / Hdiv, h = bz % Hdiv;
        A  += (size_t)b * sAb + (size_t)h * sAh;
        Bm += (size_t)b * sBb + (size_t)h * sBh;
        C  += (size_t)b * sCb + (size_t)h * sCh;
    }

    const int tid  = threadIdx.x;
    const int warp = tid >> 5;
    const int lane = tid & 31;
    const int wm   = warp >> 1;     // 0..1
    const int wn   = warp & 1;      // 0..1
    const int gid  = lane >> 2;     // 0..7
    const int tg   = lane & 3;      // 0..3

    const int row0 = blockIdx.y * BM;
    const int col0 = blockIdx.x * BM;

    const int nIter = (K + BK - 1) / BK;

    float acc[4][8][4];
#pragma unroll
    for (int mt = 0; mt < 4; mt++)
#pragma unroll
        for (int nt = 0; nt < 8; nt++)
#pragma unroll
            for (int r = 0; r < 4; r++) acc[mt][nt][r] = 0.f;

    float4 rA[4], rB[4];

    auto gloadA = [&](int k0) {
#pragma unroll
        for (int i = 0; i < 4; i++) {
            int id = tid + i * 128;         // 512 float4s: 128 m x 4 kquads
            int m  = id >> 2, kq = id & 3;
            int gr = row0 + m, gk = k0 + kq * 4;
            rA[i] = make_float4(0.f, 0.f, 0.f, 0.f);
            if (gr < M && gk < K)
                rA[i] = *(const float4*)(A + (size_t)gr * lda + gk);
        }
    };
    auto gloadB = [&](int k0) {
#pragma unroll
        for (int i = 0; i < 4; i++) {
            rB[i] = make_float4(0.f, 0.f, 0.f, 0.f);
            if (TRANSB) {
                int id = tid + i * 128;
                int n  = id >> 2, kq = id & 3;
                int gn = col0 + n, gk = k0 + kq * 4;
                if (gn < N && gk < K)
                    rB[i] = *(const float4*)(Bm + (size_t)gn * ldb + gk);
            } else {
                int id = tid + i * 128;     // 512 float4s: 16 k x 32 nquads
                int kk = id >> 5, nq = id & 31;
                int gk = k0 + kk, gn = col0 + nq * 4;
                if (gk < K && gn < N)
                    rB[i] = *(const float4*)(Bm + (size_t)gk * ldb + gn);
            }
        }
    };
    auto stsA = [&](int s) {
#pragma unroll
        for (int i = 0; i < 4; i++) {
            int id = tid + i * 128;
            int m  = id >> 2, kq = id & 3;
            float* p = &As[s][(kq * 4) * GLD + m];
            p[0 * GLD] = f2tf32f(rA[i].x);
            p[1 * GLD] = f2tf32f(rA[i].y);
            p[2 * GLD] = f2tf32f(rA[i].z);
            p[3 * GLD] = f2tf32f(rA[i].w);
        }
    };
    auto stsB = [&](int s) {
#pragma unroll
        for (int i = 0; i < 4; i++) {
            if (TRANSB) {
                int id = tid + i * 128;
                int n  = id >> 2, kq = id & 3;
                float* p = &Bs[s][(kq * 4) * GLD + n];
                p[0 * GLD] = f2tf32f(rB[i].x);
                p[1 * GLD] = f2tf32f(rB[i].y);
                p[2 * GLD] = f2tf32f(rB[i].z);
                p[3 * GLD] = f2tf32f(rB[i].w);
            } else {
                int id = tid + i * 128;
                int kk = id >> 5, nq = id & 31;
                float4 v = make_float4(f2tf32f(rB[i].x), f2tf32f(rB[i].y),
                                       f2tf32f(rB[i].z), f2tf32f(rB[i].w));
                *(float4*)&Bs[s][kk * GLD + nq * 4] = v;
            }
        }
    };

    gloadA(0); gloadB(0);
    stsA(0);   stsB(0);
    __syncthreads();

    for (int it = 0; it < nIter; it++) {
        const int s = it & 1;
        if (it + 1 < nIter) { gloadA((it + 1) * BK); gloadB((it + 1) * BK); }

#pragma unroll
        for (int ks = 0; ks < 2; ks++) {
            const int kb = ks * 8;
            const float* A0 = &As[s][(kb + tg    ) * GLD];
            const float* A1 = &As[s][(kb + tg + 4) * GLD];
            const float* B0 = &Bs[s][(kb + tg    ) * GLD];
            const float* B1 = &Bs[s][(kb + tg + 4) * GLD];

            uint32_t a[4][4];
#pragma unroll
            for (int mt = 0; mt < 4; mt++) {
                int mr = wm * 64 + mt * 16 + gid;
                a[mt][0] = __float_as_uint(A0[mr    ]);
                a[mt][1] = __float_as_uint(A0[mr + 8]);
                a[mt][2] = __float_as_uint(A1[mr    ]);
                a[mt][3] = __float_as_uint(A1[mr + 8]);
            }
            uint32_t b[8][2];
#pragma unroll
            for (int nt = 0; nt < 8; nt++) {
                int nc = wn * 64 + nt * 8 + gid;
                b[nt][0] = __float_as_uint(B0[nc]);
                b[nt][1] = __float_as_uint(B1[nc]);
            }
#pragma unroll
            for (int nt = 0; nt < 8; nt++)
#pragma unroll
                for (int mt = 0; mt < 4; mt++)
                    mma_tf32(acc[mt][nt], a[mt], b[nt][0], b[nt][1]);
        }

        if (it + 1 < nIter) { stsA(s ^ 1); stsB(s ^ 1); }
        __syncthreads();
    }

#pragma unroll
    for (int mt = 0; mt < 4; mt++) {
        int gr = row0 + wm * 64 + mt * 16 + gid;
#pragma unroll
        for (int nt = 0; nt < 8; nt++) {
            int gc = col0 + wn * 64 + nt * 8 + 2 * tg;
            if (gc >= N) continue;
            float bx = 0.f, by = 0.f;
            if (bias) { bx = bias[gc]; by = bias[gc + 1]; }
#pragma unroll
            for (int rr = 0; rr < 2; rr++) {
                int r = gr + rr * 8;
                if (r >= M) continue;
                float v0 = acc[mt][nt][rr * 2 + 0] * alpha + bx;
                float v1 = acc[mt][nt][rr * 2 + 1] * alpha + by;
                *(float2*)&C[(size_t)r * ldc + gc] = make_float2(v0, v1);
            }
        }
    }
}

// --------- fused split-K reduce + bias + (optional raw copy) + rmsnorm -----
// part: [4][rows][N]. Writes raw row (if raw != nullptr) and normalized
// first NORMN cols (weight w) to normout (row stride NORMN).
__global__ __launch_bounds__(128)
void reduce_norm(const float* __restrict__ part, const float* __restrict__ bias,
                 const float* __restrict__ w, float* __restrict__ raw,
                 float* __restrict__ normout, int N, int NORMN, int total)
{
    int row = blockIdx.x, tid = threadIdx.x;
    __shared__ float buf[576];
    __shared__ float red[4];

    int n4 = N >> 2;
    float ss = 0.f;
    for (int c = tid; c < n4; c += 128) {
        size_t off = (size_t)row * N + c * 4;
        float4 s = *(const float4*)(part + off);
#pragma unroll
        for (int k = 1; k < 4; k++) {
            float4 p = *(const float4*)(part + (size_t)k * total + off);
            s.x += p.x; s.y += p.y; s.z += p.z; s.w += p.w;
        }
        if (bias) {
            s.x += bias[c * 4]; s.y += bias[c * 4 + 1];
            s.z += bias[c * 4 + 2]; s.w += bias[c * 4 + 3];
        }
        *(float4*)&buf[c * 4] = s;
        if (raw) *(float4*)(raw + off) = s;
        if (c * 4 < NORMN)
            ss += s.x * s.x + s.y * s.y + s.z * s.z + s.w * s.w;
    }
#pragma unroll
    for (int o = 16; o > 0; o >>= 1) ss += __shfl_xor_sync(0xffffffffu, ss, o);
    if ((tid & 31) == 0) red[tid >> 5] = ss;
    __syncthreads();
    ss = red[0] + red[1] + red[2] + red[3];
    float inv = rsqrtf(ss / (float)NORMN + 1e-6f);

    for (int c = tid; c < (NORMN >> 2); c += 128) {
        float4 v  = *(float4*)&buf[c * 4];
        float4 wv = *(const float4*)(w + c * 4);
        v.x *= inv * wv.x; v.y *= inv * wv.y;
        v.z *= inv * wv.z; v.w *= inv * wv.w;
        *(float4*)(normout + (size_t)row * NORMN + c * 4) = v;
    }
}

// ---------------------------------------------------------------------------
// Fused flash attention (causal): per CTA one (b,h,128-query tile).
// 8 warps x 16 query rows. 64-key tiles. tf32 mma for S=QK^T and O=P V.
// ---------------------------------------------------------------------------
#define FA_SQ_LD 136
#define FA_SK_LD 72
#define FA_SV_LD 136
#define FA_SP_LD 136
#define FA_SMEM_FLOATS (192*FA_SQ_LD + 192*FA_SK_LD + 64*FA_SV_LD + 64*FA_SP_LD)

__global__ __launch_bounds__(256)
void fa_kernel(const float* __restrict__ Qg, const float* __restrict__ Kg,
               const float* __restrict__ Vg, float* __restrict__ Og)
{
    extern __shared__ float sm[];
    float* sQ = sm;
    float* sK = sQ + 192 * FA_SQ_LD;
    float* sV = sK + 192 * FA_SK_LD;
    float* sP = sV + 64 * FA_SV_LD;

    const int qt = (int)(gridDim.x - 1 - blockIdx.x);
    const int bh = blockIdx.y;
    const int b  = bh / HH;
    const int h  = bh % HH;

    const int tid  = threadIdx.x;
    const int warp = tid >> 5;
    const int lane = tid & 31;
    const int gid  = lane >> 2;
    const int tg   = lane & 3;
    const int qr0  = warp * 16;
    const int qg0  = qt * 128;

    const float* Qbase = Qg + ((size_t)(b * SEQ + qg0) * HH + h) * DQK;
    const float* Kbase = Kg + ((size_t)(b * SEQ) * HH + h) * DQK;
    const float* Vbase = Vg + ((size_t)(b * SEQ) * HH + h) * DKV + DNOPE;

#pragma unroll
    for (int i = 0; i < 24; i++) {
        int idx = tid + i * 256;
        int row = idx / 48, c4 = idx % 48;
        float4 v = *(const float4*)(Qbase + (size_t)row * (HH * DQK) + c4 * 4);
        sQ[(c4 * 4 + 0) * FA_SQ_LD + row] = f2tf32f(v.x);
        sQ[(c4 * 4 + 1) * FA_SQ_LD + row] = f2tf32f(v.y);
        sQ[(c4 * 4 + 2) * FA_SQ_LD + row] = f2tf32f(v.z);
        sQ[(c4 * 4 + 3) * FA_SQ_LD + row] = f2tf32f(v.w);
    }

    float accO[16][4];
#pragma unroll
    for (int nt = 0; nt < 16; nt++)
#pragma unroll
        for (int r = 0; r < 4; r++) accO[nt][r] = 0.f;
    float m_i[2] = { -1e30f, -1e30f };
    float l_i[2] = { 0.f, 0.f };

    const int ktEnd = 2 * qt + 2;
    const int warpRowMax = qg0 + qr0 + 15;

    for (int kt = 0; kt < ktEnd; kt++) {
        const int kb0 = kt * 64;
        __syncthreads();

#pragma unroll
        for (int i = 0; i < 12; i++) {
            int idx = tid + i * 256;
            int key = idx / 48, c4 = idx % 48;
            float4 v = *(const float4*)(Kbase + (size_t)(kb0 + key) * (HH * DQK) + c4 * 4);
            sK[(c4 * 4 + 0) * FA_SK_LD + key] = f2tf32f(v.x);
            sK[(c4 * 4 + 1) * FA_SK_LD + key] = f2tf32f(v.y);
            sK[(c4 * 4 + 2) * FA_SK_LD + key] = f2tf32f(v.z);
            sK[(c4 * 4 + 3) * FA_SK_LD + key] = f2tf32f(v.w);
        }
#pragma unroll
        for (int i = 0; i < 8; i++) {
            int idx = tid + i * 256;
            int key = idx / 32, c4 = idx % 32;
            float4 v = *(const float4*)(Vbase + (size_t)(kb0 + key) * (HH * DKV) + c4 * 4);
            float4 t = make_float4(f2tf32f(v.x), f2tf32f(v.y), f2tf32f(v.z), f2tf32f(v.w));
            *(float4*)&sV[key * FA_SV_LD + c4 * 4] = t;
        }
        __syncthreads();

        if (kb0 > warpRowMax) continue;

        float accS[8][4];
#pragma unroll
        for (int nt = 0; nt < 8; nt++)
#pragma unroll
            for (int r = 0; r < 4; r++) accS[nt][r] = 0.f;

#pragma unroll
        for (int ks = 0; ks < 24; ks++) {
            const int kb = ks * 8;
            uint32_t a[4];
            a[0] = __float_as_uint(sQ[(kb + tg    ) * FA_SQ_LD + qr0 + gid    ]);
            a[1] = __float_as_uint(sQ[(kb + tg    ) * FA_SQ_LD + qr0 + gid + 8]);
            a[2] = __float_as_uint(sQ[(kb + tg + 4) * FA_SQ_LD + qr0 + gid    ]);
            a[3] = __float_as_uint(sQ[(kb + tg + 4) * FA_SQ_LD + qr0 + gid + 8]);
#pragma unroll
            for (int nt = 0; nt < 8; nt++) {
                uint32_t b0 = __float_as_uint(sK[(kb + tg    ) * FA_SK_LD + nt * 8 + gid]);
                uint32_t b1 = __float_as_uint(sK[(kb + tg + 4) * FA_SK_LD + nt * 8 + gid]);
                mma_tf32(accS[nt], a, b0, b1);
            }
        }

#pragma unroll
        for (int h2 = 0; h2 < 2; h2++) {
            const int rg = qg0 + qr0 + gid + 8 * h2;
            float rmax = -1e30f;
#pragma unroll
            for (int nt = 0; nt < 8; nt++) {
#pragma unroll
                for (int j = 0; j < 2; j++) {
                    int col = kb0 + nt * 8 + tg * 2 + j;
                    float s = accS[nt][h2 * 2 + j] * SCALEF;
                    if (col > rg) s = -1e30f;
                    accS[nt][h2 * 2 + j] = s;
                    rmax = fmaxf(rmax, s);
                }
            }
            rmax = fmaxf(rmax, __shfl_xor_sync(0xffffffffu, rmax, 1));
            rmax = fmaxf(rmax, __shfl_xor_sync(0xffffffffu, rmax, 2));
            float mold = m_i[h2];
            float mnew = fmaxf(mold, rmax);
            float f = expf(mold - mnew);
            float rsum = 0.f;
#pragma unroll
            for (int nt = 0; nt < 8; nt++) {
#pragma unroll
                for (int j = 0; j < 2; j++) {
                    float p = expf(accS[nt][h2 * 2 + j] - mnew);
                    accS[nt][h2 * 2 + j] = p;
                    rsum += p;
                }
            }
            rsum += __shfl_xor_sync(0xffffffffu, rsum, 1);
            rsum += __shfl_xor_sync(0xffffffffu, rsum, 2);
            l_i[h2] = l_i[h2] * f + rsum;
            m_i[h2] = mnew;
#pragma unroll
            for (int nt = 0; nt < 16; nt++) {
                accO[nt][h2 * 2 + 0] *= f;
                accO[nt][h2 * 2 + 1] *= f;
            }
#pragma unroll
            for (int nt = 0; nt < 8; nt++) {
                int cl = nt * 8 + tg * 2;
                sP[(cl    ) * FA_SP_LD + qr0 + gid + 8 * h2] = f2tf32f(accS[nt][h2 * 2 + 0]);
                sP[(cl + 1) * FA_SP_LD + qr0 + gid + 8 * h2] = f2tf32f(accS[nt][h2 * 2 + 1]);
            }
        }
        __syncwarp();

#pragma unroll
        for (int ks = 0; ks < 8; ks++) {
            const int kb = ks * 8;
            uint32_t a[4];
            a[0] = __float_as_uint(sP[(kb + tg    ) * FA_SP_LD + qr0 + gid    ]);
            a[1] = __float_as_uint(sP[(kb + tg    ) * FA_SP_LD + qr0 + gid + 8]);
            a[2] = __float_as_uint(sP[(kb + tg + 4) * FA_SP_LD + qr0 + gid    ]);
            a[3] = __float_as_uint(sP[(kb + tg + 4) * FA_SP_LD + qr0 + gid + 8]);
#pragma unroll
            for (int nt = 0; nt < 16; nt++) {
                uint32_t b0 = __float_as_uint(sV[(kb + tg    ) * FA_SV_LD + nt * 8 + gid]);
                uint32_t b1 = __float_as_uint(sV[(kb + tg + 4) * FA_SV_LD + nt * 8 + gid]);
                mma_tf32(accO[nt], a, b0, b1);
            }
        }
    }

#pragma unroll
    for (int h2 = 0; h2 < 2; h2++) {
        const int rg = qg0 + qr0 + gid + 8 * h2;
        float inv = 1.f / l_i[h2];
        float* Orow = Og + ((size_t)(b * SEQ + rg) * HH + h) * DV;
#pragma unroll
        for (int nt = 0; nt < 16; nt++) {
            float2 v = make_float2(accO[nt][h2 * 2 + 0] * inv,
                                   accO[nt][h2 * 2 + 1] * inv);
            *(float2*)&Orow[nt * 8 + tg * 2] = v;
        }
    }
}

// -------------------------- RoPE on q_pe (in place) -------------------------
__global__ void rope_q_kernel(float* __restrict__ q,
                              const float* __restrict__ fcos,
                              const float* __restrict__ fsin)
{
    int idx = blockIdx.x * blockDim.x + threadIdx.x;
    const int HALF = DROPE / 2;
    int total = BSROWS * HH * HALF;
    if (idx >= total) return;
    int i  = idx % HALF;
    int hh = (idx / HALF) % HH;
    int bs = idx / (HALF * HH);
    int s  = bs % SEQ;
    float c  = fcos[s * HALF + i];
    float sn = fsin[s * HALF + i];
    float* p = q + (size_t)bs * (HH * DQK) + hh * DQK + DNOPE + 2 * i;
    float x0 = p[0], x1 = p[1];
    p[0] = x0 * c - x1 * sn;
    p[1] = x0 * sn + x1 * c;
}

// ---------------- build K = concat(k_nope, rope(k_pe) broadcast) ------------
__global__ void build_k_kernel(const float* __restrict__ kvb,
                               const float* __restrict__ kva,
                               const float* __restrict__ fcos,
                               const float* __restrict__ fsin,
                               float* __restrict__ kk)
{
    const int HALF  = DROPE / 2;
    const int UNITS = DNOPE + HALF;
    int idx = blockIdx.x * blockDim.x + threadIdx.x;
    int total = BSROWS * HH * UNITS;
    if (idx >= total) return;
    int u  = idx % UNITS;
    int hh = (idx / UNITS) % HH;
    int bs = idx / (UNITS * HH);
    int s  = bs % SEQ;
    float* krow = kk + (size_t)bs * (HH * DQK) + hh * DQK;
    if (u < DNOPE) {
        krow[u] = kvb[(size_t)bs * (HH * DKV) + hh * DKV + u];
    } else {
        int i = u - DNOPE;
        float c  = fcos[s * HALF + i];
        float sn = fsin[s * HALF + i];
        const float* kp = kva + (size_t)bs * (KVLORA + DROPE) + KVLORA;
        float x0 = kp[2 * i], x1 = kp[2 * i + 1];
        krow[DNOPE + 2 * i]     = x0 * c - x1 * sn;
        krow[DNOPE + 2 * i + 1] = x0 * sn + x1 * c;
    }
}

// -----------------------------------------------------------------------------
extern "C" void kernel_launch(void* const* d_in, const int* in_sizes, int n_in,
                              void* d_out, int out_size)
{
    (void)in_sizes; (void)n_in; (void)out_size;
    const float* x        = (const float*)d_in[0];
    const float* wq_a_w   = (const float*)d_in[1];
    const float* wq_a_b   = (const float*)d_in[2];
    const float* q_norm_w = (const float*)d_in[3];
    const float* wq_b_w   = (const float*)d_in[4];
    const float* wkv_a_w  = (const float*)d_in[5];
    const float* wkv_a_b  = (const float*)d_in[6];
    const float* kv_norm_w= (const float*)d_in[7];
    const float* wkv_b_w  = (const float*)d_in[8];
    const float* wo_w     = (const float*)d_in[9];
    const float* fcos     = (const float*)d_in[10];
    const float* fsin     = (const float*)d_in[11];
    float* out = (float*)d_out;

    float *qn, *qbuf, *kva, *kvn, *kvb, *kmat, *ao, *part;
    cudaGetSymbolAddress((void**)&qn,   g_qn);
    cudaGetSymbolAddress((void**)&qbuf, g_q);
    cudaGetSymbolAddress((void**)&kva,  g_kva);
    cudaGetSymbolAddress((void**)&kvn,  g_kvn);
    cudaGetSymbolAddress((void**)&kvb,  g_kvb);
    cudaGetSymbolAddress((void**)&kmat, g_k);
    cudaGetSymbolAddress((void**)&ao,   g_ao);
    cudaGetSymbolAddress((void**)&part, g_part);

    cudaFuncSetAttribute(fa_kernel, cudaFuncAttributeMaxDynamicSharedMemorySize,
                         FA_SMEM_FLOATS * 4);

    dim3 blk(128);

    // 1. q_a = x @ wq_a_w (split-K x4)           [4096,512] K=2048
    gemm_tf32<false><<<dim3(4,32,4), blk>>>(
        x, wq_a_w, nullptr, part,
        BSROWS, QLORA, DIM, DIM, QLORA, QLORA, 1.f, 1, 4,
        0,0,0,0, (long)BSROWS*QLORA, 0);

    // 2. fused reduce + bias + rmsnorm -> qn
    reduce_norm<<<BSROWS, 128>>>(part, wq_a_b, q_norm_w, nullptr, qn,
                                 QLORA, QLORA, BSROWS*QLORA);

    // 3. q = q_norm @ wq_b_w                     [4096,3072] K=512
    gemm_tf32<false><<<dim3(24,32,1), blk>>>(
        qn, wq_b_w, nullptr, qbuf,
        BSROWS, HH*DQK, QLORA, QLORA, HH*DQK, HH*DQK, 1.f, 1, 1,
        0,0,0,0,0,0);

    // 4. kv_full = x @ wkv_a_w (split-K x4)      [4096,576] K=2048
    gemm_tf32<false><<<dim3(5,32,4), blk>>>(
        x, wkv_a_w, nullptr, part,
        BSROWS, KVLORA+DROPE, DIM, DIM, KVLORA+DROPE, KVLORA+DROPE, 1.f, 1, 4,
        0,0,0,0, (long)BSROWS*(KVLORA+DROPE), 0);

    // 5. fused reduce + bias + raw(kva) + rmsnorm -> kvn
    reduce_norm<<<BSROWS, 128>>>(part, wkv_a_b, kv_norm_w, kva, kvn,
                                 KVLORA+DROPE, KVLORA, BSROWS*(KVLORA+DROPE));

    // 6. kv_b = kv_norm @ wkv_b_w                [4096,4096] K=512
    gemm_tf32<false><<<dim3(32,32,1), blk>>>(
        kvn, wkv_b_w, nullptr, kvb,
        BSROWS, HH*DKV, KVLORA, KVLORA, HH*DKV, HH*DKV, 1.f, 1, 1,
        0,0,0,0,0,0);

    // 7. RoPE on q_pe (in place)
    {
        int tot = BSROWS * HH * (DROPE/2);
        rope_q_kernel<<<(tot + 255)/256, 256>>>(qbuf, fcos, fsin);
    }

    // 8. build K = [k_nope | rope(k_pe)]
    {
        int tot = BSROWS * HH * (DNOPE + DROPE/2);
        build_k_kernel<<<(tot + 255)/256, 256>>>(kvb, kva, fcos, fsin, kmat);
    }

    // 9. fused flash attention -> ao
    fa_kernel<<<dim3(SEQ/128, BB*HH), 256, FA_SMEM_FLOATS * 4>>>(
        qbuf, kmat, kvb, ao);

    // 10. out = attn_out @ wo_w                  [4096,2048] K=2048
    gemm_tf32<false><<<dim3(16,32,1), blk>>>(
        ao, wo_w, nullptr, out,
        BSROWS, DIM, HH*DV, HH*DV, DIM, DIM, 1.f, 1, 1,
        0,0,0,0,0,0);
}

// round 14
// speedup vs baseline: 1.2595x; 1.1094x over previous
#include <cuda_runtime.h>
#include <math.h>
#include <stdint.h>

// Problem constants
#define BB     2
#define SEQ    2048
#define DIM    2048
#define HH     16
#define QLORA  512
#define KVLORA 512
#define DNOPE  128
#define DROPE  64
#define DV     128
#define DQK    192          // DNOPE + DROPE
#define DKV    256          // DNOPE + DV
#define BSROWS (BB*SEQ)     // 4096
#define SCALEF 0.07216878364870323f   // 192^-0.5

// ---------------- scratch (device globals; allocation-free) ----------------
__device__ float g_qn  [(size_t)BSROWS*QLORA];
__device__ float g_q   [(size_t)BSROWS*HH*DQK];
__device__ float g_kva [(size_t)BSROWS*(KVLORA+DROPE)];
__device__ float g_kvn [(size_t)BSROWS*KVLORA];
__device__ float g_kvb [(size_t)BSROWS*HH*DKV];
__device__ float g_k   [(size_t)BSROWS*HH*DQK];
__device__ float g_ao  [(size_t)BSROWS*HH*DV];
__device__ float g_part[(size_t)4*BSROWS*(KVLORA+DROPE)];   // split-K partials
// tf32-rounded operand copies
__device__ float g_xt  [(size_t)BSROWS*DIM];
__device__ float g_wqa [(size_t)DIM*QLORA];
__device__ float g_wqb [(size_t)QLORA*HH*DQK];
__device__ float g_wkva[(size_t)DIM*(KVLORA+DROPE)];
__device__ float g_wkvb[(size_t)KVLORA*HH*DKV];
__device__ float g_wo  [(size_t)HH*DV*DIM];

// --------------------------- tf32 helpers ----------------------------------
__device__ __forceinline__ uint32_t f2tf32(float x) {
    uint32_t r;
    asm("cvt.rna.tf32.f32 %0, %1;" : "=r"(r) : "f"(x));
    return r;
}
__device__ __forceinline__ float f2tf32f(float x) {
    return __uint_as_float(f2tf32(x));
}
__device__ __forceinline__ void mma_tf32(float* c, const uint32_t* a,
                                         uint32_t b0, uint32_t b1) {
    asm volatile(
        "mma.sync.aligned.m16n8k8.row.col.f32.tf32.tf32.f32 "
        "{%0,%1,%2,%3}, {%4,%5,%6,%7}, {%8,%9}, {%0,%1,%2,%3};"
        : "+f"(c[0]), "+f"(c[1]), "+f"(c[2]), "+f"(c[3])
        : "r"(a[0]), "r"(a[1]), "r"(a[2]), "r"(a[3]), "r"(b0), "r"(b1));
}
__device__ __forceinline__ void cp16(uint32_t dst, const void* src, bool p) {
    int sz = p ? 16 : 0;
    asm volatile("cp.async.cg.shared.global [%0], [%1], 16, %2;"
                 :: "r"(dst), "l"(src), "r"(sz) : "memory");
}
#define CP_COMMIT() asm volatile("cp.async.commit_group;" ::: "memory")
#define CP_WAIT2()  asm volatile("cp.async.wait_group 2;" ::: "memory")

// ----------------------- tf32 rounding pass --------------------------------
__global__ void round_tf32_kernel(const float* __restrict__ in,
                                  float* __restrict__ out, int n4)
{
    int i = blockIdx.x * blockDim.x + threadIdx.x;
    if (i >= n4) return;
    float4 v = *(const float4*)(in + i * 4);
    v.x = f2tf32f(v.x); v.y = f2tf32f(v.y);
    v.z = f2tf32f(v.z); v.w = f2tf32f(v.w);
    *(float4*)(out + i * 4) = v;
}

// ---------------------------------------------------------------------------
// GEMM v3: C = A @ B.  Inputs MUST be pre-rounded to tf32.
// CTA 128x128x16, 128 threads = 4 warps (2Mx2N), warp tile 64x64.
// 4-stage cp.async pipeline; A smem m-major (LD 20), B smem k-major (LD 136).
// M, K assumed multiples of 128/16; N guarded (zero-fill + store guard).
// splitK>1: blockIdx.z slices K; partial C at bz*sCsplit.
// ---------------------------------------------------------------------------
#define LDA_S 20
#define LDB_S 136
#define A_STG (128*LDA_S)
#define B_STG (16*LDB_S)
#define STG_FLOATS (A_STG + B_STG)
#define GEMM_SMEM (4*STG_FLOATS*4)

__global__ __launch_bounds__(128)
void gemm_v3(const float* __restrict__ A, const float* __restrict__ Bm,
             float* __restrict__ C,
             int M, int N, int K, int lda, int ldb, int ldc,
             int splitK, long sCsplit)
{
    extern __shared__ float smem[];
    const uint32_t sbase = (uint32_t)__cvta_generic_to_shared(smem);

    if (splitK > 1) {
        int chunk = K / splitK;
        A  += (size_t)blockIdx.z * chunk;
        Bm += (size_t)blockIdx.z * chunk * ldb;
        C  += (size_t)blockIdx.z * sCsplit;
        K = chunk;
    }

    const int tid  = threadIdx.x;
    const int warp = tid >> 5;
    const int lane = tid & 31;
    const int wm   = warp >> 1;
    const int wn   = warp & 1;
    const int gid  = lane >> 2;
    const int tg   = lane & 3;

    const int row0 = blockIdx.y * 128;
    const int col0 = blockIdx.x * 128;
    const int nIter = K >> 4;

    // per-thread load descriptors (4 x 16B for A, 4 x 16B for B per stage)
    const float* aSrc[4]; uint32_t aDst[4];
    const float* bSrc[4]; uint32_t bDst[4]; bool bPred[4];
#pragma unroll
    for (int i = 0; i < 4; i++) {
        int id = tid + i * 128;
        int m  = id >> 2, kq = id & 3;
        aSrc[i] = A + (size_t)(row0 + m) * lda + kq * 4;
        aDst[i] = (m * LDA_S + kq * 4) * 4;
        int kk = id >> 5, nq = id & 31;
        bSrc[i] = Bm + (size_t)kk * ldb + col0 + nq * 4;
        bDst[i] = (A_STG + kk * LDB_S + nq * 4) * 4;
        bPred[i] = (col0 + nq * 4) < N;
    }

    auto issue = [&](int stage, int tile) {
        uint32_t sb = sbase + stage * (STG_FLOATS * 4);
        const size_t aOff = (size_t)tile * 16;
        const size_t bOff = (size_t)tile * 16 * ldb;
#pragma unroll
        for (int i = 0; i < 4; i++) cp16(sb + aDst[i], aSrc[i] + aOff, true);
#pragma unroll
        for (int i = 0; i < 4; i++) cp16(sb + bDst[i], bSrc[i] + bOff, bPred[i]);
        CP_COMMIT();
    };

    // prologue: 3 tiles in flight (nIter >= 32 for all our shapes)
    issue(0, 0); issue(1, 1); issue(2, 2);

    float acc[4][8][4];
#pragma unroll
    for (int mt = 0; mt < 4; mt++)
#pragma unroll
        for (int nt = 0; nt < 8; nt++)
#pragma unroll
            for (int r = 0; r < 4; r++) acc[mt][nt][r] = 0.f;

    for (int it = 0; it < nIter; it++) {
        CP_WAIT2();
        __syncthreads();

        const float* sA = smem + (it & 3) * STG_FLOATS;
        const float* sB = sA + A_STG;

#pragma unroll
        for (int ks = 0; ks < 2; ks++) {
            const int kb = ks * 8;
            uint32_t a[4][4];
#pragma unroll
            for (int mt = 0; mt < 4; mt++) {
                int mr = wm * 64 + mt * 16 + gid;
                a[mt][0] = __float_as_uint(sA[(mr    ) * LDA_S + kb + tg    ]);
                a[mt][1] = __float_as_uint(sA[(mr + 8) * LDA_S + kb + tg    ]);
                a[mt][2] = __float_as_uint(sA[(mr    ) * LDA_S + kb + tg + 4]);
                a[mt][3] = __float_as_uint(sA[(mr + 8) * LDA_S + kb + tg + 4]);
            }
            uint32_t b[8][2];
#pragma unroll
            for (int nt = 0; nt < 8; nt++) {
                int nc = wn * 64 + nt * 8 + gid;
                b[nt][0] = __float_as_uint(sB[(kb + tg    ) * LDB_S + nc]);
                b[nt][1] = __float_as_uint(sB[(kb + tg + 4) * LDB_S + nc]);
            }
#pragma unroll
            for (int nt = 0; nt < 8; nt++)
#pragma unroll
                for (int mt = 0; mt < 4; mt++)
                    mma_tf32(acc[mt][nt], a[mt], b[nt][0], b[nt][1]);
        }

        __syncthreads();
        if (it + 3 < nIter) issue((it + 3) & 3, it + 3);
    }

#pragma unroll
    for (int mt = 0; mt < 4; mt++) {
        int gr = row0 + wm * 64 + mt * 16 + gid;
#pragma unroll
        for (int nt = 0; nt < 8; nt++) {
            int gc = col0 + wn * 64 + nt * 8 + 2 * tg;
            if (gc >= N) continue;
#pragma unroll
            for (int rr = 0; rr < 2; rr++) {
                int r = gr + rr * 8;
                *(float2*)&C[(size_t)r * ldc + gc] =
                    make_float2(acc[mt][nt][rr * 2 + 0], acc[mt][nt][rr * 2 + 1]);
            }
        }
    }
}

// --------- fused split-K reduce + bias + (optional raw copy) + rmsnorm -----
// normout is written tf32-rounded (it feeds a GEMM); raw is full fp32.
__global__ __launch_bounds__(128)
void reduce_norm(const float* __restrict__ part, const float* __restrict__ bias,
                 const float* __restrict__ w, float* __restrict__ raw,
                 float* __restrict__ normout, int N, int NORMN, int total)
{
    int row = blockIdx.x, tid = threadIdx.x;
    __shared__ float buf[576];
    __shared__ float red[4];

    int n4 = N >> 2;
    float ss = 0.f;
    for (int c = tid; c < n4; c += 128) {
        size_t off = (size_t)row * N + c * 4;
        float4 s = *(const float4*)(part + off);
#pragma unroll
        for (int k = 1; k < 4; k++) {
            float4 p = *(const float4*)(part + (size_t)k * total + off);
            s.x += p.x; s.y += p.y; s.z += p.z; s.w += p.w;
        }
        if (bias) {
            s.x += bias[c * 4]; s.y += bias[c * 4 + 1];
            s.z += bias[c * 4 + 2]; s.w += bias[c * 4 + 3];
        }
        *(float4*)&buf[c * 4] = s;
        if (raw) *(float4*)(raw + off) = s;
        if (c * 4 < NORMN)
            ss += s.x * s.x + s.y * s.y + s.z * s.z + s.w * s.w;
    }
#pragma unroll
    for (int o = 16; o > 0; o >>= 1) ss += __shfl_xor_sync(0xffffffffu, ss, o);
    if ((tid & 31) == 0) red[tid >> 5] = ss;
    __syncthreads();
    ss = red[0] + red[1] + red[2] + red[3];
    float inv = rsqrtf(ss / (float)NORMN + 1e-6f);

    for (int c = tid; c < (NORMN >> 2); c += 128) {
        float4 v  = *(float4*)&buf[c * 4];
        float4 wv = *(const float4*)(w + c * 4);
        v.x = f2tf32f(v.x * inv * wv.x); v.y = f2tf32f(v.y * inv * wv.y);
        v.z = f2tf32f(v.z * inv * wv.z); v.w = f2tf32f(v.w * inv * wv.w);
        *(float4*)(normout + (size_t)row * NORMN + c * 4) = v;
    }
}

// ---------------------------------------------------------------------------
// Fused flash attention (causal): per CTA one (b,h,128-query tile).
// 8 warps x 16 query rows. 64-key tiles. tf32 mma for S=QK^T and O=P V.
// Output written tf32-rounded (feeds the wo GEMM).
// ---------------------------------------------------------------------------
#define FA_SQ_LD 136
#define FA_SK_LD 72
#define FA_SV_LD 136
#define FA_SP_LD 136
#define FA_SMEM_FLOATS (192*FA_SQ_LD + 192*FA_SK_LD + 64*FA_SV_LD + 64*FA_SP_LD)

__global__ __launch_bounds__(256)
void fa_kernel(const float* __restrict__ Qg, const float* __restrict__ Kg,
               const float* __restrict__ Vg, float* __restrict__ Og)
{
    extern __shared__ float sm[];
    float* sQ = sm;
    float* sK = sQ + 192 * FA_SQ_LD;
    float* sV = sK + 192 * FA_SK_LD;
    float* sP = sV + 64 * FA_SV_LD;

    const int qt = (int)(gridDim.x - 1 - blockIdx.x);
    const int bh = blockIdx.y;
    const int b  = bh / HH;
    const int h  = bh % HH;

    const int tid  = threadIdx.x;
    const int warp = tid >> 5;
    const int lane = tid & 31;
    const int gid  = lane >> 2;
    const int tg   = lane & 3;
    const int qr0  = warp * 16;
    const int qg0  = qt * 128;

    const float* Qbase = Qg + ((size_t)(b * SEQ + qg0) * HH + h) * DQK;
    const float* Kbase = Kg + ((size_t)(b * SEQ) * HH + h) * DQK;
    const float* Vbase = Vg + ((size_t)(b * SEQ) * HH + h) * DKV + DNOPE;

#pragma unroll
    for (int i = 0; i < 24; i++) {
        int idx = tid + i * 256;
        int row = idx / 48, c4 = idx % 48;
        float4 v = *(const float4*)(Qbase + (size_t)row * (HH * DQK) + c4 * 4);
        sQ[(c4 * 4 + 0) * FA_SQ_LD + row] = f2tf32f(v.x);
        sQ[(c4 * 4 + 1) * FA_SQ_LD + row] = f2tf32f(v.y);
        sQ[(c4 * 4 + 2) * FA_SQ_LD + row] = f2tf32f(v.z);
        sQ[(c4 * 4 + 3) * FA_SQ_LD + row] = f2tf32f(v.w);
    }

    float accO[16][4];
#pragma unroll
    for (int nt = 0; nt < 16; nt++)
#pragma unroll
        for (int r = 0; r < 4; r++) accO[nt][r] = 0.f;
    float m_i[2] = { -1e30f, -1e30f };
    float l_i[2] = { 0.f, 0.f };

    const int ktEnd = 2 * qt + 2;
    const int warpRowMax = qg0 + qr0 + 15;

    for (int kt = 0; kt < ktEnd; kt++) {
        const int kb0 = kt * 64;
        __syncthreads();

#pragma unroll
        for (int i = 0; i < 12; i++) {
            int idx = tid + i * 256;
            int key = idx / 48, c4 = idx % 48;
            float4 v = *(const float4*)(Kbase + (size_t)(kb0 + key) * (HH * DQK) + c4 * 4);
            sK[(c4 * 4 + 0) * FA_SK_LD + key] = f2tf32f(v.x);
            sK[(c4 * 4 + 1) * FA_SK_LD + key] = f2tf32f(v.y);
            sK[(c4 * 4 + 2) * FA_SK_LD + key] = f2tf32f(v.z);
            sK[(c4 * 4 + 3) * FA_SK_LD + key] = f2tf32f(v.w);
        }
#pragma unroll
        for (int i = 0; i < 8; i++) {
            int idx = tid + i * 256;
            int key = idx / 32, c4 = idx % 32;
            float4 v = *(const float4*)(Vbase + (size_t)(kb0 + key) * (HH * DKV) + c4 * 4);
            float4 t = make_float4(f2tf32f(v.x), f2tf32f(v.y), f2tf32f(v.z), f2tf32f(v.w));
            *(float4*)&sV[key * FA_SV_LD + c4 * 4] = t;
        }
        __syncthreads();

        if (kb0 > warpRowMax) continue;

        float accS[8][4];
#pragma unroll
        for (int nt = 0; nt < 8; nt++)
#pragma unroll
            for (int r = 0; r < 4; r++) accS[nt][r] = 0.f;

#pragma unroll
        for (int ks = 0; ks < 24; ks++) {
            const int kb = ks * 8;
            uint32_t a[4];
            a[0] = __float_as_uint(sQ[(kb + tg    ) * FA_SQ_LD + qr0 + gid    ]);
            a[1] = __float_as_uint(sQ[(kb + tg    ) * FA_SQ_LD + qr0 + gid + 8]);
            a[2] = __float_as_uint(sQ[(kb + tg + 4) * FA_SQ_LD + qr0 + gid    ]);
            a[3] = __float_as_uint(sQ[(kb + tg + 4) * FA_SQ_LD + qr0 + gid + 8]);
#pragma unroll
            for (int nt = 0; nt < 8; nt++) {
                uint32_t b0 = __float_as_uint(sK[(kb + tg    ) * FA_SK_LD + nt * 8 + gid]);
                uint32_t b1 = __float_as_uint(sK[(kb + tg + 4) * FA_SK_LD + nt * 8 + gid]);
                mma_tf32(accS[nt], a, b0, b1);
            }
        }

#pragma unroll
        for (int h2 = 0; h2 < 2; h2++) {
            const int rg = qg0 + qr0 + gid + 8 * h2;
            float rmax = -1e30f;
#pragma unroll
            for (int nt = 0; nt < 8; nt++) {
#pragma unroll
                for (int j = 0; j < 2; j++) {
                    int col = kb0 + nt * 8 + tg * 2 + j;
                    float s = accS[nt][h2 * 2 + j] * SCALEF;
                    if (col > rg) s = -1e30f;
                    accS[nt][h2 * 2 + j] = s;
                    rmax = fmaxf(rmax, s);
                }
            }
            rmax = fmaxf(rmax, __shfl_xor_sync(0xffffffffu, rmax, 1));
            rmax = fmaxf(rmax, __shfl_xor_sync(0xffffffffu, rmax, 2));
            float mold = m_i[h2];
            float mnew = fmaxf(mold, rmax);
            float f = expf(mold - mnew);
            float rsum = 0.f;
#pragma unroll
            for (int nt = 0; nt < 8; nt++) {
#pragma unroll
                for (int j = 0; j < 2; j++) {
                    float p = expf(accS[nt][h2 * 2 + j] - mnew);
                    accS[nt][h2 * 2 + j] = p;
                    rsum += p;
                }
            }
            rsum += __shfl_xor_sync(0xffffffffu, rsum, 1);
            rsum += __shfl_xor_sync(0xffffffffu, rsum, 2);
            l_i[h2] = l_i[h2] * f + rsum;
            m_i[h2] = mnew;
#pragma unroll
            for (int nt = 0; nt < 16; nt++) {
                accO[nt][h2 * 2 + 0] *= f;
                accO[nt][h2 * 2 + 1] *= f;
            }
#pragma unroll
            for (int nt = 0; nt < 8; nt++) {
                int cl = nt * 8 + tg * 2;
                sP[(cl    ) * FA_SP_LD + qr0 + gid + 8 * h2] = f2tf32f(accS[nt][h2 * 2 + 0]);
                sP[(cl + 1) * FA_SP_LD + qr0 + gid + 8 * h2] = f2tf32f(accS[nt][h2 * 2 + 1]);
            }
        }
        __syncwarp();

#pragma unroll
        for (int ks = 0; ks < 8; ks++) {
            const int kb = ks * 8;
            uint32_t a[4];
            a[0] = __float_as_uint(sP[(kb + tg    ) * FA_SP_LD + qr0 + gid    ]);
            a[1] = __float_as_uint(sP[(kb + tg    ) * FA_SP_LD + qr0 + gid + 8]);
            a[2] = __float_as_uint(sP[(kb + tg + 4) * FA_SP_LD + qr0 + gid    ]);
            a[3] = __float_as_uint(sP[(kb + tg + 4) * FA_SP_LD + qr0 + gid + 8]);
#pragma unroll
            for (int nt = 0; nt < 16; nt++) {
                uint32_t b0 = __float_as_uint(sV[(kb + tg    ) * FA_SV_LD + nt * 8 + gid]);
                uint32_t b1 = __float_as_uint(sV[(kb + tg + 4) * FA_SV_LD + nt * 8 + gid]);
                mma_tf32(accO[nt], a, b0, b1);
            }
        }
    }

#pragma unroll
    for (int h2 = 0; h2 < 2; h2++) {
        const int rg = qg0 + qr0 + gid + 8 * h2;
        float inv = 1.f / l_i[h2];
        float* Orow = Og + ((size_t)(b * SEQ + rg) * HH + h) * DV;
#pragma unroll
        for (int nt = 0; nt < 16; nt++) {
            float2 v = make_float2(f2tf32f(accO[nt][h2 * 2 + 0] * inv),
                                   f2tf32f(accO[nt][h2 * 2 + 1] * inv));
            *(float2*)&Orow[nt * 8 + tg * 2] = v;
        }
    }
}

// -------------------------- RoPE on q_pe (in place) -------------------------
__global__ void rope_q_kernel(float* __restrict__ q,
                              const float* __restrict__ fcos,
                              const float* __restrict__ fsin)
{
    int idx = blockIdx.x * blockDim.x + threadIdx.x;
    const int HALF = DROPE / 2;
    int total = BSROWS * HH * HALF;
    if (idx >= total) return;
    int i  = idx % HALF;
    int hh = (idx / HALF) % HH;
    int bs = idx / (HALF * HH);
    int s  = bs % SEQ;
    float c  = fcos[s * HALF + i];
    float sn = fsin[s * HALF + i];
    float* p = q + (size_t)bs * (HH * DQK) + hh * DQK + DNOPE + 2 * i;
    float x0 = p[0], x1 = p[1];
    p[0] = x0 * c - x1 * sn;
    p[1] = x0 * sn + x1 * c;
}

// ---------------- build K = concat(k_nope, rope(k_pe) broadcast) ------------
__global__ void build_k_kernel(const float* __restrict__ kvb,
                               const float* __restrict__ kva,
                               const float* __restrict__ fcos,
                               const float* __restrict__ fsin,
                               float* __restrict__ kk)
{
    const int HALF  = DROPE / 2;
    const int UNITS = DNOPE + HALF;
    int idx = blockIdx.x * blockDim.x + threadIdx.x;
    int total = BSROWS * HH * UNITS;
    if (idx >= total) return;
    int u  = idx % UNITS;
    int hh = (idx / UNITS) % HH;
    int bs = idx / (UNITS * HH);
    int s  = bs % SEQ;
    float* krow = kk + (size_t)bs * (HH * DQK) + hh * DQK;
    if (u < DNOPE) {
        krow[u] = kvb[(size_t)bs * (HH * DKV) + hh * DKV + u];
    } else {
        int i = u - DNOPE;
        float c  = fcos[s * HALF + i];
        float sn = fsin[s * HALF + i];
        const float* kp = kva + (size_t)bs * (KVLORA + DROPE) + KVLORA;
        float x0 = kp[2 * i], x1 = kp[2 * i + 1];
        krow[DNOPE + 2 * i]     = x0 * c - x1 * sn;
        krow[DNOPE + 2 * i + 1] = x0 * sn + x1 * c;
    }
}

// -----------------------------------------------------------------------------
extern "C" void kernel_launch(void* const* d_in, const int* in_sizes, int n_in,
                              void* d_out, int out_size)
{
    (void)in_sizes; (void)n_in; (void)out_size;
    const float* x        = (const float*)d_in[0];
    const float* wq_a_w   = (const float*)d_in[1];
    const float* wq_a_b   = (const float*)d_in[2];
    const float* q_norm_w = (const float*)d_in[3];
    const float* wq_b_w   = (const float*)d_in[4];
    const float* wkv_a_w  = (const float*)d_in[5];
    const float* wkv_a_b  = (const float*)d_in[6];
    const float* kv_norm_w= (const float*)d_in[7];
    const float* wkv_b_w  = (const float*)d_in[8];
    const float* wo_w     = (const float*)d_in[9];
    const float* fcos     = (const float*)d_in[10];
    const float* fsin     = (const float*)d_in[11];
    float* out = (float*)d_out;

    float *qn, *qbuf, *kva, *kvn, *kvb, *kmat, *ao, *part;
    float *xt, *wqa, *wqb, *wkva, *wkvb, *wo;
    cudaGetSymbolAddress((void**)&qn,   g_qn);
    cudaGetSymbolAddress((void**)&qbuf, g_q);
    cudaGetSymbolAddress((void**)&kva,  g_kva);
    cudaGetSymbolAddress((void**)&kvn,  g_kvn);
    cudaGetSymbolAddress((void**)&kvb,  g_kvb);
    cudaGetSymbolAddress((void**)&kmat, g_k);
    cudaGetSymbolAddress((void**)&ao,   g_ao);
    cudaGetSymbolAddress((void**)&part, g_part);
    cudaGetSymbolAddress((void**)&xt,   g_xt);
    cudaGetSymbolAddress((void**)&wqa,  g_wqa);
    cudaGetSymbolAddress((void**)&wqb,  g_wqb);
    cudaGetSymbolAddress((void**)&wkva, g_wkva);
    cudaGetSymbolAddress((void**)&wkvb, g_wkvb);
    cudaGetSymbolAddress((void**)&wo,   g_wo);

    cudaFuncSetAttribute(fa_kernel, cudaFuncAttributeMaxDynamicSharedMemorySize,
                         FA_SMEM_FLOATS * 4);
    cudaFuncSetAttribute(gemm_v3, cudaFuncAttributeMaxDynamicSharedMemorySize,
                         GEMM_SMEM);

    // 0. tf32-round operands (idempotent wrt the per-mma rounding we replaced)
    auto round_in = [&](const float* src, float* dst, size_t n) {
        int n4 = (int)(n / 4);
        round_tf32_kernel<<<(n4 + 255) / 256, 256>>>(src, dst, n4);
    };
    round_in(x,       xt,   (size_t)BSROWS * DIM);
    round_in(wq_a_w,  wqa,  (size_t)DIM * QLORA);
    round_in(wq_b_w,  wqb,  (size_t)QLORA * HH * DQK);
    round_in(wkv_a_w, wkva, (size_t)DIM * (KVLORA + DROPE));
    round_in(wkv_b_w, wkvb, (size_t)KVLORA * HH * DKV);
    round_in(wo_w,    wo,   (size_t)HH * DV * DIM);

    dim3 blk(128);

    // 1. q_a = xt @ wqa (split-K x4)             [4096,512] K=2048
    gemm_v3<<<dim3(4,32,4), blk, GEMM_SMEM>>>(
        xt, wqa, part, BSROWS, QLORA, DIM, DIM, QLORA, QLORA,
        4, (long)BSROWS*QLORA);

    // 2. fused reduce + bias + rmsnorm -> qn (tf32)
    reduce_norm<<<BSROWS, 128>>>(part, wq_a_b, q_norm_w, nullptr, qn,
                                 QLORA, QLORA, BSROWS*QLORA);

    // 3. q = qn @ wqb                            [4096,3072] K=512
    gemm_v3<<<dim3(24,32,1), blk, GEMM_SMEM>>>(
        qn, wqb, qbuf, BSROWS, HH*DQK, QLORA, QLORA, HH*DQK, HH*DQK, 1, 0);

    // 4. kv_full = xt @ wkva (split-K x4)        [4096,576] K=2048
    gemm_v3<<<dim3(5,32,4), blk, GEMM_SMEM>>>(
        xt, wkva, part, BSROWS, KVLORA+DROPE, DIM, DIM, KVLORA+DROPE, KVLORA+DROPE,
        4, (long)BSROWS*(KVLORA+DROPE));

    // 5. fused reduce + bias + raw(kva) + rmsnorm -> kvn (tf32)
    reduce_norm<<<BSROWS, 128>>>(part, wkv_a_b, kv_norm_w, kva, kvn,
                                 KVLORA+DROPE, KVLORA, BSROWS*(KVLORA+DROPE));

    // 6. kv_b = kvn @ wkvb                       [4096,4096] K=512
    gemm_v3<<<dim3(32,32,1), blk, GEMM_SMEM>>>(
        kvn, wkvb, kvb, BSROWS, HH*DKV, KVLORA, KVLORA, HH*DKV, HH*DKV, 1, 0);

    // 7. RoPE on q_pe (in place)
    {
        int tot = BSROWS * HH * (DROPE/2);
        rope_q_kernel<<<(tot + 255)/256, 256>>>(qbuf, fcos, fsin);
    }

    // 8. build K = [k_nope | rope(k_pe)]
    {
        int tot = BSROWS * HH * (DNOPE + DROPE/2);
        build_k_kernel<<<(tot + 255)/256, 256>>>(kvb, kva, fcos, fsin, kmat);
    }

    // 9. fused flash attention -> ao (tf32-rounded output)
    fa_kernel<<<dim3(SEQ/128, BB*HH), 256, FA_SMEM_FLOATS * 4>>>(
        qbuf, kmat, kvb, ao);

    // 10. out = ao @ wo                          [4096,2048] K=2048
    gemm_v3<<<dim3(16,32,1), blk, GEMM_SMEM>>>(
        ao, wo, out, BSROWS, DIM, HH*DV, HH*DV, DIM, DIM, 1, 0);
}